// round 5
// baseline (speedup 1.0000x reference)
#include <cuda_runtime.h>
#include <cstdint>

#define N_PIX 1600
#define CCH   512
#define CORR  256
#define BATCH 16
#define NTILE 50    // N_PIX / 32

// ---------------- scratch (static __device__ arrays; allocation-free) -------
__device__ float g_inTe  [BATCH * N_PIX * CCH];            // exemplar^T [p][c] (tf32)
__device__ float g_inTq  [BATCH * N_PIX * CCH];            // query^T    [p][c] (tf32)
__device__ float g_qcorr [BATCH * N_PIX * CORR];           // (tf32)
__device__ float g_ecorr [BATCH * N_PIX * CORR];           // (tf32)
__device__ float g_E     [(long)BATCH * N_PIX * N_PIX];    // exp(A) (tf32)
__device__ float g_Et    [(long)BATCH * N_PIX * N_PIX];    // E^T    (tf32)
__device__ float g_prow  [BATCH * NTILE * N_PIX];          // partial row sums
__device__ float g_pcol  [BATCH * NTILE * N_PIX];          // partial col sums
__device__ float g_rsE   [BATCH * N_PIX];                  // 1/rowsum(E)
__device__ float g_rsEt  [BATCH * N_PIX];                  // 1/colsum(E)
__device__ float g_esc   [BATCH * CCH * N_PIX];            // exemplar*invColsum (tf32)
__device__ float g_qsc   [BATCH * CCH * N_PIX];            // query*invRowsum (tf32)
__device__ float g_attTe [BATCH * N_PIX * CCH];            // (tf32)
__device__ float g_attTq [BATCH * N_PIX * CCH];            // (tf32)
__device__ float g_wT    [2 * 9 * CCH * CCH];              // [which][kyx][o][c] (tf32)
__device__ float g_w1    [2 * CORR * CCH];                 // (tf32)

// ---------------- helpers -----------------------------------------------------
__device__ __forceinline__ void mma8(float4& d, const uint32_t a[4],
                                     const uint32_t b[2]) {
    asm volatile(
        "mma.sync.aligned.m16n8k8.row.col.f32.tf32.tf32.f32 "
        "{%0,%1,%2,%3}, {%4,%5,%6,%7}, {%8,%9}, {%0,%1,%2,%3};"
        : "+f"(d.x), "+f"(d.y), "+f"(d.z), "+f"(d.w)
        : "r"(a[0]), "r"(a[1]), "r"(a[2]), "r"(a[3]), "r"(b[0]), "r"(b[1]));
}
__device__ __forceinline__ float cvt1(float v) {
    asm("cvt.rna.tf32.f32 %0, %0;" : "+f"(v));
    return v;
}
__device__ __forceinline__ float4 cvt4(float4 v) {
    v.x = cvt1(v.x); v.y = cvt1(v.y); v.z = cvt1(v.z); v.w = cvt1(v.w);
    return v;
}
__device__ __forceinline__ uint32_t s2u(const void* p) {
    return (uint32_t)__cvta_generic_to_shared(p);
}
__device__ __forceinline__ void cpasync16(uint32_t dst, const void* src,
                                          uint32_t sz) {
    asm volatile("cp.async.cg.shared.global [%0], [%1], 16, %2;"
                 :: "r"(dst), "l"(src), "r"(sz));
}
#define CP_COMMIT() asm volatile("cp.async.commit_group;" ::: "memory")
#define CP_WAIT(n)  asm volatile("cp.async.wait_group %0;" :: "n"(n) : "memory")

// smem geometry (floats)
#define PITCH    36
#define A_FL     (128 * PITCH)
#define B_FL     (256 * PITCH)
#define STAGE_FL (A_FL + B_FL)
#define STAGE_B  (STAGE_FL * 4)
#define SMEM_B   (2 * STAGE_B)

// ================= GEMM mainloop core (shared by all tf32 GEMMs) =============
struct GemmCore {
    const float *aptr[4], *bptr[8];
    uint32_t asz[4], bsz[8], adst[4], bdst[8];
    float4 acc[4][8];
    int wm, wn, lg, lt;

    __device__ __forceinline__ void init_thread(int tid) {
        const int lane = tid & 31, wid = tid >> 5;
        wm = wid >> 2; wn = wid & 3; lg = lane >> 2; lt = lane & 3;
#pragma unroll
        for (int i = 0; i < 4; i++)
#pragma unroll
            for (int j = 0; j < 8; j++) acc[i][j] = make_float4(0.f, 0.f, 0.f, 0.f);
    }
    __device__ __forceinline__ void setup(int tid, const float* A, const float* B,
                                          int K, int MA, int NB, int m0, int n0) {
        const int lrow = tid >> 3, lf4 = tid & 7;
#pragma unroll
        for (int it = 0; it < 4; it++) {
            int row = lrow + it * 32;
            aptr[it] = A + (long)(m0 + row) * K + lf4 * 4;
            asz[it] = (m0 + row) < MA ? 16u : 0u;
            adst[it] = row * (PITCH * 4) + lf4 * 16;
        }
#pragma unroll
        for (int it = 0; it < 8; it++) {
            int row = lrow + it * 32;
            bptr[it] = B + (long)(n0 + row) * K + lf4 * 4;
            bsz[it] = (n0 + row) < NB ? 16u : 0u;
            bdst[it] = A_FL * 4 + row * (PITCH * 4) + lf4 * 16;
        }
    }
    __device__ __forceinline__ void issue(uint32_t sa, int koff) {
#pragma unroll
        for (int it = 0; it < 4; it++)
            cpasync16(sa + adst[it], aptr[it] + koff, asz[it]);
#pragma unroll
        for (int it = 0; it < 8; it++)
            cpasync16(sa + bdst[it], bptr[it] + koff, bsz[it]);
        CP_COMMIT();
    }
    __device__ __forceinline__ void compute(const float* As) {
        const float* Bs = As + A_FL;
#pragma unroll
        for (int ks = 0; ks < 4; ks++) {
            uint32_t af[4][4], bf[8][2];
#pragma unroll
            for (int mt = 0; mt < 4; mt++) {
                const float* p = As + (wm * 64 + mt * 16 + lg) * PITCH + ks * 8 + lt;
                af[mt][0] = __float_as_uint(p[0]);
                af[mt][1] = __float_as_uint(p[8 * PITCH]);
                af[mt][2] = __float_as_uint(p[4]);
                af[mt][3] = __float_as_uint(p[8 * PITCH + 4]);
            }
#pragma unroll
            for (int nt = 0; nt < 8; nt++) {
                const float* p = Bs + (wn * 64 + nt * 8 + lg) * PITCH + ks * 8 + lt;
                bf[nt][0] = __float_as_uint(p[0]);
                bf[nt][1] = __float_as_uint(p[4]);
            }
#pragma unroll
            for (int mt = 0; mt < 4; mt++)
#pragma unroll
                for (int nt = 0; nt < 8; nt++) mma8(acc[mt][nt], af[mt], bf[nt]);
        }
    }
    __device__ __forceinline__ void mainloop(float* sm, uint32_t smb, int nk) {
        issue(smb, 0);
        for (int ck = 0; ck < nk; ck++) {
            if (ck + 1 < nk) {
                issue(smb + ((ck + 1) & 1) * STAGE_B, (ck + 1) * 32);
                CP_WAIT(1);
            } else {
                CP_WAIT(0);
            }
            __syncthreads();
            compute(sm + (ck & 1) * STAGE_FL);
            __syncthreads();
        }
    }
    template<bool DO_EXP>
    __device__ __forceinline__ void epilogue(float* C, int ldc, int MA, int NB,
                                             int m0, int n0) {
#pragma unroll
        for (int mt = 0; mt < 4; mt++) {
            const int r = m0 + wm * 64 + mt * 16 + lg;
#pragma unroll
            for (int nt = 0; nt < 8; nt++) {
                const int n = n0 + wn * 64 + nt * 8 + 2 * lt;
                float4 v = acc[mt][nt];
                if (DO_EXP) {
                    v.x = __expf(v.x); v.y = __expf(v.y);
                    v.z = __expf(v.z); v.w = __expf(v.w);
                }
                v = cvt4(v);
                if (n < NB) {
                    if (r < MA)
                        *(float2*)(C + (long)r * ldc + n) = make_float2(v.x, v.y);
                    if (r + 8 < MA)
                        *(float2*)(C + (long)(r + 8) * ldc + n) = make_float2(v.z, v.w);
                }
            }
        }
    }
};

// -------- single-source GEMM (used for E = exp(ecorr x qcorr^T)) -------------
template<bool DO_EXP>
__global__ void __launch_bounds__(256, 1)
gemm_mma(const float* __restrict__ A, const float* __restrict__ B,
         float* __restrict__ C, int K, int MA, int NB, int ldc,
         long bA, long bB, long bC)
{
    extern __shared__ float sm[];
    GemmCore g;
    g.init_thread(threadIdx.x);
    A += (long)blockIdx.z * bA;
    B += (long)blockIdx.z * bB;
    C += (long)blockIdx.z * bC;
    const int m0 = blockIdx.y * 128, n0 = blockIdx.x * 256;
    g.setup(threadIdx.x, A, B, K, MA, NB, m0, n0);
    g.mainloop(sm, s2u(sm), K >> 5);
    g.epilogue<DO_EXP>(C, ldc, MA, NB, m0, n0);
}

// -------- dual-source GEMM: z = batch + 16*which selects operand set ---------
__global__ void __launch_bounds__(256, 1)
gemm_mma2(const float* __restrict__ A0, const float* __restrict__ B0,
          float* __restrict__ C0, long bA0, long bB0, long bC0,
          const float* __restrict__ A1, const float* __restrict__ B1,
          float* __restrict__ C1, long bA1, long bB1, long bC1,
          int K, int MA, int NB, int ldc)
{
    extern __shared__ float sm[];
    GemmCore g;
    g.init_thread(threadIdx.x);
    const int z = blockIdx.z;
    const int b = z & 15, which = z >> 4;
    const float* A = which ? (A1 + (long)b * bA1) : (A0 + (long)b * bA0);
    const float* B = which ? (B1 + (long)b * bB1) : (B0 + (long)b * bB0);
    float* C       = which ? (C1 + (long)b * bC1) : (C0 + (long)b * bC0);
    const int m0 = blockIdx.y * 128, n0 = blockIdx.x * 256;
    g.setup(threadIdx.x, A, B, K, MA, NB, m0, n0);
    g.mainloop(sm, s2u(sm), K >> 5);
    g.epilogue<false>(C, ldc, MA, NB, m0, n0);
}

// ---------------- conv 3x3 SAME via implicit GEMM ----------------------------
__global__ void __launch_bounds__(256, 1)
conv_mma(const float* __restrict__ attTe, const float* __restrict__ attTq,
         const float* __restrict__ wT, float* __restrict__ out)
{
    extern __shared__ float sm[];
    const uint32_t smb = s2u(sm);
    const int tid = threadIdx.x;
    const int z = blockIdx.z;
    const int b = z & 15, which = z >> 4;
    const float* inT = (which ? attTq : attTe) + (long)b * N_PIX * CCH;
    const float* wbase = wT + (long)which * 9 * CCH * CCH;
    const int m0 = blockIdx.y * 128;
    const int n0 = blockIdx.x * 256;

    GemmCore g;
    g.init_thread(tid);

    const int lrow = tid >> 3, lf4 = tid & 7;
    uint32_t adst[4], aoff[4];
#pragma unroll
    for (int it = 0; it < 4; it++) {
        int row = lrow + it * 32;
        aoff[it] = (m0 + row) * CCH + lf4 * 4;
        adst[it] = row * (PITCH * 4) + lf4 * 16;
    }
    int py_[8], px_[8];
    bool pv_[8];
    uint32_t bdst[8];
#pragma unroll
    for (int it = 0; it < 8; it++) {
        int row = lrow + it * 32;
        int p = n0 + row;
        py_[it] = p / 40; px_[it] = p % 40;
        pv_[it] = (p < N_PIX);
        bdst[it] = A_FL * 4 + row * (PITCH * 4) + lf4 * 16;
    }

    const int nk = 144;
    auto issue = [&](int ck, uint32_t sa) {
        const int kyx = ck >> 4;
        const int cc = (ck & 15) * 32;
        const int dy = kyx / 3 - 1, dx = kyx % 3 - 1;
        const float* wk = wbase + (long)kyx * (CCH * CCH) + cc;
#pragma unroll
        for (int it = 0; it < 4; it++)
            cpasync16(sa + adst[it], wk + aoff[it], 16u);
#pragma unroll
        for (int it = 0; it < 8; it++) {
            int ys = py_[it] + dy, xs = px_[it] + dx;
            bool ok = pv_[it] && (unsigned)ys < 40u && (unsigned)xs < 40u;
            const float* src = inT + (long)(ys * 40 + xs) * CCH + cc + lf4 * 4;
            cpasync16(sa + bdst[it], src, ok ? 16u : 0u);
        }
        CP_COMMIT();
    };

    issue(0, smb);
    for (int ck = 0; ck < nk; ck++) {
        if (ck + 1 < nk) {
            issue(ck + 1, smb + ((ck + 1) & 1) * STAGE_B);
            CP_WAIT(1);
        } else {
            CP_WAIT(0);
        }
        __syncthreads();
        g.compute(sm + (ck & 1) * STAGE_FL);
        __syncthreads();
    }

    float* obase = out + ((long)b * 2 * CCH + (long)which * CCH) * N_PIX;
#pragma unroll
    for (int mt = 0; mt < 4; mt++) {
        const int r = m0 + g.wm * 64 + mt * 16 + g.lg;
#pragma unroll
        for (int nt = 0; nt < 8; nt++) {
            const int n = n0 + g.wn * 64 + nt * 8 + 2 * g.lt;
            if (n < N_PIX) {
                float4 v = g.acc[mt][nt];
                *(float2*)(obase + (long)r * N_PIX + n) = make_float2(v.x, v.y);
                *(float2*)(obase + (long)(r + 8) * N_PIX + n) = make_float2(v.z, v.w);
            }
        }
    }
}

// ------------- dual input transpose [c][p] -> [p][c] with tf32 cvt -----------
__global__ void transpose_in(const float* __restrict__ s0, float* __restrict__ d0,
                             const float* __restrict__ s1, float* __restrict__ d1)
{
    __shared__ float t[32][33];
    const int z = blockIdx.z;
    const int b = z & 15, which = z >> 4;
    const long CN = (long)CCH * N_PIX;
    const float* src = (which ? s1 : s0) + (long)b * CN;
    float* dst = (which ? d1 : d0) + (long)b * CN;
    const int x0 = blockIdx.x * 32, y0 = blockIdx.y * 32;
    const int tx = threadIdx.x, ty = threadIdx.y;
#pragma unroll
    for (int r = 0; r < 32; r += 8)
        t[ty + r][tx] = src[(long)(y0 + ty + r) * N_PIX + x0 + tx];
    __syncthreads();
#pragma unroll
    for (int r = 0; r < 32; r += 8)
        dst[(long)(x0 + ty + r) * CCH + y0 + tx] = cvt1(t[tx][ty + r]);
}

// ------- E transpose + per-tile row/col partial sums (deterministic) ---------
__global__ void transpose_es(const float* __restrict__ E, float* __restrict__ Et,
                             float* __restrict__ prow, float* __restrict__ pcol)
{
    __shared__ float t[32][33];
    const long NN = (long)N_PIX * N_PIX;
    const int bz = blockIdx.z;
    const float* src = E + bz * NN;
    float* dst = Et + bz * NN;
    const int x0 = blockIdx.x * 32, y0 = blockIdx.y * 32;
    const int tx = threadIdx.x, ty = threadIdx.y;   // (32, 8)
#pragma unroll
    for (int r = 0; r < 32; r += 8)
        t[ty + r][tx] = src[(long)(y0 + ty + r) * N_PIX + x0 + tx];
    __syncthreads();

    if (ty == 0) {          // row sums: row tx of tile (global row y0+tx)
        float s = 0.f;
#pragma unroll 8
        for (int j = 0; j < 32; j++) s += t[tx][j];
        prow[((bz * NTILE) + blockIdx.x) * N_PIX + y0 + tx] = s;
    } else if (ty == 1) {   // col sums: col tx of tile (global col x0+tx)
        float s = 0.f;
#pragma unroll 8
        for (int i = 0; i < 32; i++) s += t[i][tx];
        pcol[((bz * NTILE) + blockIdx.y) * N_PIX + x0 + tx] = s;
    }
#pragma unroll
    for (int r = 0; r < 32; r += 8)
        dst[(long)(x0 + ty + r) * N_PIX + y0 + tx] = t[tx][ty + r];
}

// ------------- reduce partials over 50 tiles and invert ----------------------
__global__ void reduce_inv(const float* __restrict__ prow,
                           const float* __restrict__ pcol,
                           float* __restrict__ rsE, float* __restrict__ rsEt)
{
    int idx = blockIdx.x * 256 + threadIdx.x;   // b*N_PIX + n
    if (idx >= BATCH * N_PIX) return;
    const int b = idx / N_PIX, n = idx % N_PIX;
    const float* src = (blockIdx.y ? pcol : prow) + (long)b * NTILE * N_PIX + n;
    float s = 0.f;
#pragma unroll 10
    for (int tgt = 0; tgt < NTILE; tgt++) s += src[(long)tgt * N_PIX];
    (blockIdx.y ? rsEt : rsE)[idx] = 1.f / s;
}

// esc = exemplar * invColsum(E)[i]; qsc = query * invRowsum(E)[i]  (tf32 out)
__global__ void scale_kernel(const float* __restrict__ ex,
                             const float* __restrict__ qu,
                             const float* __restrict__ invCs,
                             const float* __restrict__ invRs,
                             float* __restrict__ e2, float* __restrict__ q2)
{
    long idx = (long)blockIdx.x * 256 + threadIdx.x;
    if (idx >= (long)BATCH * CCH * N_PIX) return;
    int i = (int)(idx % N_PIX);
    int b = (int)(idx / ((long)CCH * N_PIX));
    e2[idx] = cvt1(ex[idx] * invCs[b * N_PIX + i]);
    q2[idx] = cvt1(qu[idx] * invRs[b * N_PIX + i]);
}

// ---------------- conv weights OIHW -> [which][kyx][o][c] (tf32) -------------
__global__ void wtrans_kernel(const float* __restrict__ w1,
                              const float* __restrict__ w2,
                              float* __restrict__ wT)
{
    long idx = (long)blockIdx.x * 256 + threadIdx.x;
    const long per = 9L * CCH * CCH;
    if (idx >= 2 * per) return;
    int c = (int)(idx & (CCH - 1));
    long t = idx >> 9;
    int o = (int)(t & (CCH - 1));
    long t2 = t >> 9;
    int kyx = (int)(t2 % 9);
    int which = (int)(t2 / 9);
    const float* w = which ? w2 : w1;
    wT[idx] = cvt1(w[((long)o * CCH + c) * 9 + kyx]);
}

// ---------------- 1x1 weights: copy w_q, w_e with tf32 rounding --------------
__global__ void w1cvt_kernel(const float* __restrict__ wq,
                             const float* __restrict__ we,
                             float* __restrict__ dst)
{
    int idx = blockIdx.x * 256 + threadIdx.x;
    if (idx >= 2 * CORR * CCH) return;
    const float* w = (idx < CORR * CCH) ? wq : we;
    dst[idx] = cvt1(w[idx < CORR * CCH ? idx : idx - CORR * CCH]);
}

// ---------------- launch ------------------------------------------------------
extern "C" void kernel_launch(void* const* d_in, const int* in_sizes, int n_in,
                              void* d_out, int out_size)
{
    const float* exemplar = (const float*)d_in[0];
    const float* query    = (const float*)d_in[1];
    const float* w_e      = (const float*)d_in[2];
    const float* w_q      = (const float*)d_in[3];
    const float* w_c1     = (const float*)d_in[4];
    const float* w_c2     = (const float*)d_in[5];
    float* out = (float*)d_out;

    float *inTe, *inTq, *qcorr, *ecorr, *E, *Et, *prow, *pcol, *rsE, *rsEt,
          *esc, *qsc, *attTe, *attTq, *wT, *w1;
    cudaGetSymbolAddress((void**)&inTe,  g_inTe);
    cudaGetSymbolAddress((void**)&inTq,  g_inTq);
    cudaGetSymbolAddress((void**)&qcorr, g_qcorr);
    cudaGetSymbolAddress((void**)&ecorr, g_ecorr);
    cudaGetSymbolAddress((void**)&E,     g_E);
    cudaGetSymbolAddress((void**)&Et,    g_Et);
    cudaGetSymbolAddress((void**)&prow,  g_prow);
    cudaGetSymbolAddress((void**)&pcol,  g_pcol);
    cudaGetSymbolAddress((void**)&rsE,   g_rsE);
    cudaGetSymbolAddress((void**)&rsEt,  g_rsEt);
    cudaGetSymbolAddress((void**)&esc,   g_esc);
    cudaGetSymbolAddress((void**)&qsc,   g_qsc);
    cudaGetSymbolAddress((void**)&attTe, g_attTe);
    cudaGetSymbolAddress((void**)&attTq, g_attTq);
    cudaGetSymbolAddress((void**)&wT,    g_wT);
    cudaGetSymbolAddress((void**)&w1,    g_w1);

    cudaFuncSetAttribute(gemm_mma<false>,
                         cudaFuncAttributeMaxDynamicSharedMemorySize, SMEM_B);
    cudaFuncSetAttribute(gemm_mma<true>,
                         cudaFuncAttributeMaxDynamicSharedMemorySize, SMEM_B);
    cudaFuncSetAttribute(gemm_mma2,
                         cudaFuncAttributeMaxDynamicSharedMemorySize, SMEM_B);
    cudaFuncSetAttribute(conv_mma,
                         cudaFuncAttributeMaxDynamicSharedMemorySize, SMEM_B);

    const long NN = (long)N_PIX * N_PIX;
    const long CN = (long)CCH * N_PIX;
    const long NK = (long)N_PIX * CORR;

    // weight re-layouts (tf32)
    wtrans_kernel<<<(unsigned)((2L * 9 * CCH * CCH + 255) / 256), 256>>>(w_c1, w_c2, wT);
    w1cvt_kernel<<<(2 * CORR * CCH + 255) / 256, 256>>>(w_q, w_e, w1);

    // input transposes [c][p] -> [p][c] (tf32), both in one launch
    transpose_in<<<dim3(NTILE, 16, 32), dim3(32, 8)>>>(exemplar, inTe, query, inTq);

    // 1x1 projections (both in one launch): corr[p][o] = sum_c inT[p][c]*w[o][c]
    gemm_mma2<<<dim3(1, 13, 32), 256, SMEM_B>>>(
        inTq, w1, qcorr, CN, 0L, NK,
        inTe, w1 + (long)CORR * CCH, ecorr, CN, 0L, NK,
        CCH, N_PIX, CORR, CORR);

    // E[n][m] = exp( sum_k ecorr[n][k] * qcorr[m][k] )
    gemm_mma<true><<<dim3(7, 13, BATCH), 256, SMEM_B>>>(
        ecorr, qcorr, E, CORR, N_PIX, N_PIX, N_PIX, NK, NK, NN);

    // Et = E^T, plus per-tile row/col partial sums
    transpose_es<<<dim3(NTILE, NTILE, BATCH), dim3(32, 8)>>>(E, Et, prow, pcol);
    reduce_inv<<<dim3((BATCH * N_PIX + 255) / 256, 2), 256>>>(prow, pcol, rsE, rsEt);

    // scaled inputs (softmax denominators folded into the small operand)
    scale_kernel<<<(unsigned)(((long)BATCH * CCH * N_PIX + 255) / 256), 256>>>(
        exemplar, query, rsEt, rsE, esc, qsc);

    // attention GEMMs, operand-swapped -> transposed outputs directly:
    //   which0: attTq[j][c] = sum_i E[j][i]  * esc[c][i]
    //   which1: attTe[j][c] = sum_i Et[j][i] * qsc[c][i]
    gemm_mma2<<<dim3(2, 13, 32), 256, SMEM_B>>>(
        E,  esc, attTq, NN, CN, CN,
        Et, qsc, attTe, NN, CN, CN,
        N_PIX, N_PIX, CCH, CCH);

    // 3x3 SAME convs into concatenated output
    conv_mma<<<dim3(7, 4, 2 * BATCH), 256, SMEM_B>>>(attTe, attTq, wT, out);
}

// round 6
// speedup vs baseline: 1.5104x; 1.5104x over previous
#include <cuda_runtime.h>
#include <cstdint>

#define N_PIX 1600
#define CCH   512
#define CORR  256
#define BATCH 16
#define NTILE 50    // N_PIX / 32

// ---------------- scratch (static __device__ arrays; allocation-free) -------
__device__ float g_inTe  [BATCH * N_PIX * CCH];            // exemplar^T [p][c] (tf32)
__device__ float g_inTq  [BATCH * N_PIX * CCH];            // query^T    [p][c] (tf32)
__device__ float g_qcorr [BATCH * N_PIX * CORR];           // (tf32)
__device__ float g_ecorr [BATCH * N_PIX * CORR];           // (tf32)
__device__ float g_E     [(long)BATCH * N_PIX * N_PIX];    // exp(A) (tf32)
__device__ float g_Et    [(long)BATCH * N_PIX * N_PIX];    // E^T    (tf32)
__device__ float g_prow  [BATCH * NTILE * N_PIX];          // partial row sums
__device__ float g_pcol  [BATCH * NTILE * N_PIX];          // partial col sums
__device__ float g_rsE   [BATCH * N_PIX];                  // 1/rowsum(E)
__device__ float g_rsEt  [BATCH * N_PIX];                  // 1/colsum(E)
__device__ float g_esc   [BATCH * CCH * N_PIX];            // exemplar*invColsum (tf32)
__device__ float g_qsc   [BATCH * CCH * N_PIX];            // query*invRowsum (tf32)
__device__ float g_attTe [BATCH * N_PIX * CCH];            // (tf32)
__device__ float g_attTq [BATCH * N_PIX * CCH];            // (tf32)
__device__ float g_wT    [2 * 9 * CCH * CCH];              // [which][kyx][o][c] (tf32)
__device__ float g_w1    [2 * CORR * CCH];                 // (tf32)

// ---------------- helpers -----------------------------------------------------
__device__ __forceinline__ void mma8(float4& d, const uint32_t a[4],
                                     const uint32_t b[2]) {
    asm volatile(
        "mma.sync.aligned.m16n8k8.row.col.f32.tf32.tf32.f32 "
        "{%0,%1,%2,%3}, {%4,%5,%6,%7}, {%8,%9}, {%0,%1,%2,%3};"
        : "+f"(d.x), "+f"(d.y), "+f"(d.z), "+f"(d.w)
        : "r"(a[0]), "r"(a[1]), "r"(a[2]), "r"(a[3]), "r"(b[0]), "r"(b[1]));
}
__device__ __forceinline__ float cvt1(float v) {
    asm("cvt.rna.tf32.f32 %0, %0;" : "+f"(v));
    return v;
}
__device__ __forceinline__ float4 cvt4(float4 v) {
    v.x = cvt1(v.x); v.y = cvt1(v.y); v.z = cvt1(v.z); v.w = cvt1(v.w);
    return v;
}
__device__ __forceinline__ uint32_t s2u(const void* p) {
    return (uint32_t)__cvta_generic_to_shared(p);
}
__device__ __forceinline__ void cpasync16(uint32_t dst, const void* src,
                                          uint32_t sz) {
    asm volatile("cp.async.cg.shared.global [%0], [%1], 16, %2;"
                 :: "r"(dst), "l"(src), "r"(sz));
}
#define CP_COMMIT() asm volatile("cp.async.commit_group;" ::: "memory")
#define CP_WAIT(n)  asm volatile("cp.async.wait_group %0;" :: "n"(n) : "memory")

// smem geometry (floats)
#define PITCH    36
#define A_FL     (128 * PITCH)           // 4608
#define B_FL     (256 * PITCH)           // 9216
#define STAGE_FL (A_FL + B_FL)           // 13824
#define STAGE_B  (STAGE_FL * 4)          // 55296
#define SMEM_B   (2 * STAGE_B)           // 110592

// ---------------- tf32 GEMM: C[m][n] = sum_k A[m][k]*B[n][k] ------------------
// CTA 128x256xK32, 8 warps (2x4), warp tile 64x64, cp.async double buffer.
// Flat structure (R4 codegen: ~124 regs). Operands tf32-rounded; output rounded.
template<bool DO_EXP>
__global__ void __launch_bounds__(256, 1)
gemm_mma(const float* __restrict__ A, const float* __restrict__ B,
         float* __restrict__ C, int K, int MA, int NB, int ldc,
         long bA, long bB, long bC)
{
    extern __shared__ float sm[];
    const uint32_t smb = s2u(sm);
    const int tid = threadIdx.x;
    const int lane = tid & 31, wid = tid >> 5;
    const int wm = wid >> 2, wn = wid & 3;
    const int lg = lane >> 2, lt = lane & 3;
    A += (long)blockIdx.z * bA;
    B += (long)blockIdx.z * bB;
    C += (long)blockIdx.z * bC;
    const int m0 = blockIdx.y * 128, n0 = blockIdx.x * 256;

    const int lrow = tid >> 3;
    const int lf4  = tid & 7;

    const float* aptr[4];
    uint32_t asz[4], adst[4];
#pragma unroll
    for (int it = 0; it < 4; it++) {
        int row = lrow + it * 32;
        aptr[it] = A + (long)(m0 + row) * K + lf4 * 4;
        asz[it] = (m0 + row) < MA ? 16u : 0u;
        adst[it] = row * (PITCH * 4) + lf4 * 16;
    }
    const float* bptr[8];
    uint32_t bsz[8], bdst[8];
#pragma unroll
    for (int it = 0; it < 8; it++) {
        int row = lrow + it * 32;
        bptr[it] = B + (long)(n0 + row) * K + lf4 * 4;
        bsz[it] = (n0 + row) < NB ? 16u : 0u;
        bdst[it] = A_FL * 4 + row * (PITCH * 4) + lf4 * 16;
    }

    float4 acc[4][8];
#pragma unroll
    for (int i = 0; i < 4; i++)
#pragma unroll
        for (int j = 0; j < 8; j++) acc[i][j] = make_float4(0.f, 0.f, 0.f, 0.f);

    const int nk = K >> 5;

    {
        uint32_t sa = smb;
#pragma unroll
        for (int it = 0; it < 4; it++) cpasync16(sa + adst[it], aptr[it], asz[it]);
#pragma unroll
        for (int it = 0; it < 8; it++) cpasync16(sa + bdst[it], bptr[it], bsz[it]);
        CP_COMMIT();
    }

    for (int ck = 0; ck < nk; ck++) {
        if (ck + 1 < nk) {
            const uint32_t sa = smb + ((ck + 1) & 1) * STAGE_B;
            const int koff = (ck + 1) * 32;
#pragma unroll
            for (int it = 0; it < 4; it++)
                cpasync16(sa + adst[it], aptr[it] + koff, asz[it]);
#pragma unroll
            for (int it = 0; it < 8; it++)
                cpasync16(sa + bdst[it], bptr[it] + koff, bsz[it]);
            CP_COMMIT();
            CP_WAIT(1);
        } else {
            CP_WAIT(0);
        }
        __syncthreads();

        const float* As = sm + (ck & 1) * STAGE_FL;
        const float* Bs = As + A_FL;
#pragma unroll
        for (int ks = 0; ks < 4; ks++) {
            uint32_t af[4][4], bf[8][2];
#pragma unroll
            for (int mt = 0; mt < 4; mt++) {
                const float* p = As + (wm * 64 + mt * 16 + lg) * PITCH + ks * 8 + lt;
                af[mt][0] = __float_as_uint(p[0]);
                af[mt][1] = __float_as_uint(p[8 * PITCH]);
                af[mt][2] = __float_as_uint(p[4]);
                af[mt][3] = __float_as_uint(p[8 * PITCH + 4]);
            }
#pragma unroll
            for (int nt = 0; nt < 8; nt++) {
                const float* p = Bs + (wn * 64 + nt * 8 + lg) * PITCH + ks * 8 + lt;
                bf[nt][0] = __float_as_uint(p[0]);
                bf[nt][1] = __float_as_uint(p[4]);
            }
#pragma unroll
            for (int mt = 0; mt < 4; mt++)
#pragma unroll
                for (int nt = 0; nt < 8; nt++) mma8(acc[mt][nt], af[mt], bf[nt]);
        }
        __syncthreads();
    }

#pragma unroll
    for (int mt = 0; mt < 4; mt++) {
        const int r = m0 + wm * 64 + mt * 16 + lg;
#pragma unroll
        for (int nt = 0; nt < 8; nt++) {
            const int n = n0 + wn * 64 + nt * 8 + 2 * lt;
            float4 v = acc[mt][nt];
            if (DO_EXP) {
                v.x = __expf(v.x); v.y = __expf(v.y);
                v.z = __expf(v.z); v.w = __expf(v.w);
            }
            v = cvt4(v);
            if (n < NB) {
                if (r < MA)
                    *(float2*)(C + (long)r * ldc + n) = make_float2(v.x, v.y);
                if (r + 8 < MA)
                    *(float2*)(C + (long)(r + 8) * ldc + n) = make_float2(v.z, v.w);
            }
        }
    }
}

// ---------------- conv 3x3 SAME via implicit GEMM (flat, as in R4) -----------
__global__ void __launch_bounds__(256, 1)
conv_mma(const float* __restrict__ attTe, const float* __restrict__ attTq,
         const float* __restrict__ wT, float* __restrict__ out)
{
    extern __shared__ float sm[];
    const uint32_t smb = s2u(sm);
    const int tid = threadIdx.x;
    const int lane = tid & 31, wid = tid >> 5;
    const int wm = wid >> 2, wn = wid & 3;
    const int lg = lane >> 2, lt = lane & 3;
    const int z = blockIdx.z;
    const int b = z & 15, which = z >> 4;
    const float* inT = (which ? attTq : attTe) + (long)b * N_PIX * CCH;
    const float* wbase = wT + (long)which * 9 * CCH * CCH;
    const int m0 = blockIdx.y * 128;
    const int n0 = blockIdx.x * 256;

    const int lrow = tid >> 3;
    const int lf4  = tid & 7;

    uint32_t adst[4], aoff[4];
#pragma unroll
    for (int it = 0; it < 4; it++) {
        int row = lrow + it * 32;
        aoff[it] = (m0 + row) * CCH + lf4 * 4;
        adst[it] = row * (PITCH * 4) + lf4 * 16;
    }
    int py_[8], px_[8];
    bool pv_[8];
    uint32_t bdst[8];
#pragma unroll
    for (int it = 0; it < 8; it++) {
        int row = lrow + it * 32;
        int p = n0 + row;
        py_[it] = p / 40; px_[it] = p % 40;
        pv_[it] = (p < N_PIX);
        bdst[it] = A_FL * 4 + row * (PITCH * 4) + lf4 * 16;
    }

    float4 acc[4][8];
#pragma unroll
    for (int i = 0; i < 4; i++)
#pragma unroll
        for (int j = 0; j < 8; j++) acc[i][j] = make_float4(0.f, 0.f, 0.f, 0.f);

    const int nk = 144;

    auto issue = [&](int ck, uint32_t sa) {
        const int kyx = ck >> 4;
        const int cc = (ck & 15) * 32;
        const int dy = kyx / 3 - 1, dx = kyx % 3 - 1;
        const float* wk = wbase + (long)kyx * (CCH * CCH) + cc;
#pragma unroll
        for (int it = 0; it < 4; it++)
            cpasync16(sa + adst[it], wk + aoff[it], 16u);
#pragma unroll
        for (int it = 0; it < 8; it++) {
            int ys = py_[it] + dy, xs = px_[it] + dx;
            bool ok = pv_[it] && (unsigned)ys < 40u && (unsigned)xs < 40u;
            const float* src = inT + (long)(ys * 40 + xs) * CCH + cc + lf4 * 4;
            cpasync16(sa + bdst[it], src, ok ? 16u : 0u);
        }
        CP_COMMIT();
    };

    issue(0, smb);
    for (int ck = 0; ck < nk; ck++) {
        if (ck + 1 < nk) {
            issue(ck + 1, smb + ((ck + 1) & 1) * STAGE_B);
            CP_WAIT(1);
        } else {
            CP_WAIT(0);
        }
        __syncthreads();

        const float* As = sm + (ck & 1) * STAGE_FL;
        const float* Bs = As + A_FL;
#pragma unroll
        for (int ks = 0; ks < 4; ks++) {
            uint32_t af[4][4], bf[8][2];
#pragma unroll
            for (int mt = 0; mt < 4; mt++) {
                const float* p = As + (wm * 64 + mt * 16 + lg) * PITCH + ks * 8 + lt;
                af[mt][0] = __float_as_uint(p[0]);
                af[mt][1] = __float_as_uint(p[8 * PITCH]);
                af[mt][2] = __float_as_uint(p[4]);
                af[mt][3] = __float_as_uint(p[8 * PITCH + 4]);
            }
#pragma unroll
            for (int nt = 0; nt < 8; nt++) {
                const float* p = Bs + (wn * 64 + nt * 8 + lg) * PITCH + ks * 8 + lt;
                bf[nt][0] = __float_as_uint(p[0]);
                bf[nt][1] = __float_as_uint(p[4]);
            }
#pragma unroll
            for (int mt = 0; mt < 4; mt++)
#pragma unroll
                for (int nt = 0; nt < 8; nt++) mma8(acc[mt][nt], af[mt], bf[nt]);
        }
        __syncthreads();
    }

    float* obase = out + ((long)b * 2 * CCH + (long)which * CCH) * N_PIX;
#pragma unroll
    for (int mt = 0; mt < 4; mt++) {
        const int r = m0 + wm * 64 + mt * 16 + lg;
#pragma unroll
        for (int nt = 0; nt < 8; nt++) {
            const int n = n0 + wn * 64 + nt * 8 + 2 * lt;
            if (n < N_PIX) {
                float4 v = acc[mt][nt];
                *(float2*)(obase + (long)r * N_PIX + n) = make_float2(v.x, v.y);
                *(float2*)(obase + (long)(r + 8) * N_PIX + n) = make_float2(v.z, v.w);
            }
        }
    }
}

// ------------- dual input transpose [c][p] -> [p][c] with tf32 cvt -----------
__global__ void transpose_in(const float* __restrict__ s0, float* __restrict__ d0,
                             const float* __restrict__ s1, float* __restrict__ d1)
{
    __shared__ float t[32][33];
    const int z = blockIdx.z;
    const int b = z & 15, which = z >> 4;
    const long CN = (long)CCH * N_PIX;
    const float* src = (which ? s1 : s0) + (long)b * CN;
    float* dst = (which ? d1 : d0) + (long)b * CN;
    const int x0 = blockIdx.x * 32, y0 = blockIdx.y * 32;
    const int tx = threadIdx.x, ty = threadIdx.y;
#pragma unroll
    for (int r = 0; r < 32; r += 8)
        t[ty + r][tx] = src[(long)(y0 + ty + r) * N_PIX + x0 + tx];
    __syncthreads();
#pragma unroll
    for (int r = 0; r < 32; r += 8)
        dst[(long)(x0 + ty + r) * CCH + y0 + tx] = cvt1(t[tx][ty + r]);
}

// ------- E transpose + per-tile row/col partial sums (deterministic) ---------
__global__ void transpose_es(const float* __restrict__ E, float* __restrict__ Et,
                             float* __restrict__ prow, float* __restrict__ pcol)
{
    __shared__ float t[32][33];
    const long NN = (long)N_PIX * N_PIX;
    const int bz = blockIdx.z;
    const float* src = E + bz * NN;
    float* dst = Et + bz * NN;
    const int x0 = blockIdx.x * 32, y0 = blockIdx.y * 32;
    const int tx = threadIdx.x, ty = threadIdx.y;   // (32, 8)
#pragma unroll
    for (int r = 0; r < 32; r += 8)
        t[ty + r][tx] = src[(long)(y0 + ty + r) * N_PIX + x0 + tx];
    __syncthreads();

    if (ty == 0) {          // row sums (global row y0+tx)
        float s = 0.f;
#pragma unroll 8
        for (int j = 0; j < 32; j++) s += t[tx][j];
        prow[((bz * NTILE) + blockIdx.x) * N_PIX + y0 + tx] = s;
    } else if (ty == 1) {   // col sums (global col x0+tx)
        float s = 0.f;
#pragma unroll 8
        for (int i = 0; i < 32; i++) s += t[i][tx];
        pcol[((bz * NTILE) + blockIdx.y) * N_PIX + x0 + tx] = s;
    }
#pragma unroll
    for (int r = 0; r < 32; r += 8)
        dst[(long)(x0 + ty + r) * N_PIX + y0 + tx] = t[tx][ty + r];
}

// ------------- reduce partials over 50 tiles and invert ----------------------
__global__ void reduce_inv(const float* __restrict__ prow,
                           const float* __restrict__ pcol,
                           float* __restrict__ rsE, float* __restrict__ rsEt)
{
    int idx = blockIdx.x * 256 + threadIdx.x;   // b*N_PIX + n
    if (idx >= BATCH * N_PIX) return;
    const int b = idx / N_PIX, n = idx % N_PIX;
    const float* src = (blockIdx.y ? pcol : prow) + (long)b * NTILE * N_PIX + n;
    float s = 0.f;
#pragma unroll 10
    for (int tgt = 0; tgt < NTILE; tgt++) s += src[(long)tgt * N_PIX];
    (blockIdx.y ? rsEt : rsE)[idx] = 1.f / s;
}

// esc = exemplar * invColsum(E)[i]; qsc = query * invRowsum(E)[i]  (tf32 out)
__global__ void scale_kernel(const float* __restrict__ ex,
                             const float* __restrict__ qu,
                             const float* __restrict__ invCs,
                             const float* __restrict__ invRs,
                             float* __restrict__ e2, float* __restrict__ q2)
{
    long idx = (long)blockIdx.x * 256 + threadIdx.x;
    if (idx >= (long)BATCH * CCH * N_PIX) return;
    int i = (int)(idx % N_PIX);
    int b = (int)(idx / ((long)CCH * N_PIX));
    e2[idx] = cvt1(ex[idx] * invCs[b * N_PIX + i]);
    q2[idx] = cvt1(qu[idx] * invRs[b * N_PIX + i]);
}

// ---------------- conv weights OIHW -> [which][kyx][o][c] (tf32) -------------
__global__ void wtrans_kernel(const float* __restrict__ w1,
                              const float* __restrict__ w2,
                              float* __restrict__ wT)
{
    long idx = (long)blockIdx.x * 256 + threadIdx.x;
    const long per = 9L * CCH * CCH;
    if (idx >= 2 * per) return;
    int c = (int)(idx & (CCH - 1));
    long t = idx >> 9;
    int o = (int)(t & (CCH - 1));
    long t2 = t >> 9;
    int kyx = (int)(t2 % 9);
    int which = (int)(t2 / 9);
    const float* w = which ? w2 : w1;
    wT[idx] = cvt1(w[((long)o * CCH + c) * 9 + kyx]);
}

// ---------------- 1x1 weights: copy w_q, w_e with tf32 rounding --------------
__global__ void w1cvt_kernel(const float* __restrict__ wq,
                             const float* __restrict__ we,
                             float* __restrict__ dst)
{
    int idx = blockIdx.x * 256 + threadIdx.x;
    if (idx >= 2 * CORR * CCH) return;
    const float* w = (idx < CORR * CCH) ? wq : we;
    dst[idx] = cvt1(w[idx < CORR * CCH ? idx : idx - CORR * CCH]);
}

// ---------------- launch ------------------------------------------------------
extern "C" void kernel_launch(void* const* d_in, const int* in_sizes, int n_in,
                              void* d_out, int out_size)
{
    const float* exemplar = (const float*)d_in[0];
    const float* query    = (const float*)d_in[1];
    const float* w_e      = (const float*)d_in[2];
    const float* w_q      = (const float*)d_in[3];
    const float* w_c1     = (const float*)d_in[4];
    const float* w_c2     = (const float*)d_in[5];
    float* out = (float*)d_out;

    float *inTe, *inTq, *qcorr, *ecorr, *E, *Et, *prow, *pcol, *rsE, *rsEt,
          *esc, *qsc, *attTe, *attTq, *wT, *w1;
    cudaGetSymbolAddress((void**)&inTe,  g_inTe);
    cudaGetSymbolAddress((void**)&inTq,  g_inTq);
    cudaGetSymbolAddress((void**)&qcorr, g_qcorr);
    cudaGetSymbolAddress((void**)&ecorr, g_ecorr);
    cudaGetSymbolAddress((void**)&E,     g_E);
    cudaGetSymbolAddress((void**)&Et,    g_Et);
    cudaGetSymbolAddress((void**)&prow,  g_prow);
    cudaGetSymbolAddress((void**)&pcol,  g_pcol);
    cudaGetSymbolAddress((void**)&rsE,   g_rsE);
    cudaGetSymbolAddress((void**)&rsEt,  g_rsEt);
    cudaGetSymbolAddress((void**)&esc,   g_esc);
    cudaGetSymbolAddress((void**)&qsc,   g_qsc);
    cudaGetSymbolAddress((void**)&attTe, g_attTe);
    cudaGetSymbolAddress((void**)&attTq, g_attTq);
    cudaGetSymbolAddress((void**)&wT,    g_wT);
    cudaGetSymbolAddress((void**)&w1,    g_w1);

    cudaFuncSetAttribute(gemm_mma<false>,
                         cudaFuncAttributeMaxDynamicSharedMemorySize, SMEM_B);
    cudaFuncSetAttribute(gemm_mma<true>,
                         cudaFuncAttributeMaxDynamicSharedMemorySize, SMEM_B);
    cudaFuncSetAttribute(conv_mma,
                         cudaFuncAttributeMaxDynamicSharedMemorySize, SMEM_B);

    const long NN = (long)N_PIX * N_PIX;
    const long CN = (long)CCH * N_PIX;
    const long NK = (long)N_PIX * CORR;

    // weight re-layouts (tf32)
    wtrans_kernel<<<(unsigned)((2L * 9 * CCH * CCH + 255) / 256), 256>>>(w_c1, w_c2, wT);
    w1cvt_kernel<<<(2 * CORR * CCH + 255) / 256, 256>>>(w_q, w_e, w1);

    // input transposes [c][p] -> [p][c] (tf32), both in one launch
    transpose_in<<<dim3(NTILE, 16, 32), dim3(32, 8)>>>(exemplar, inTe, query, inTq);

    // 1x1 projections: corr[p][o] = sum_c inT[p][c] * w[o][c]
    gemm_mma<false><<<dim3(1, 13, BATCH), 256, SMEM_B>>>(
        inTq, w1, qcorr, CCH, N_PIX, CORR, CORR, CN, 0L, NK);
    gemm_mma<false><<<dim3(1, 13, BATCH), 256, SMEM_B>>>(
        inTe, w1 + (long)CORR * CCH, ecorr, CCH, N_PIX, CORR, CORR, CN, 0L, NK);

    // E[n][m] = exp( sum_k ecorr[n][k] * qcorr[m][k] )
    gemm_mma<true><<<dim3(7, 13, BATCH), 256, SMEM_B>>>(
        ecorr, qcorr, E, CORR, N_PIX, N_PIX, N_PIX, NK, NK, NN);

    // Et = E^T, fused per-tile row/col partial sums
    transpose_es<<<dim3(NTILE, NTILE, BATCH), dim3(32, 8)>>>(E, Et, prow, pcol);
    reduce_inv<<<dim3((BATCH * N_PIX + 255) / 256, 2), 256>>>(prow, pcol, rsE, rsEt);

    // scaled inputs (softmax denominators folded into the small operand)
    scale_kernel<<<(unsigned)(((long)BATCH * CCH * N_PIX + 255) / 256), 256>>>(
        exemplar, query, rsEt, rsE, esc, qsc);

    // attention GEMMs, operand-swapped -> transposed outputs directly:
    //   attTq[j][c] = sum_i E[j][i]  * esc[c][i]
    //   attTe[j][c] = sum_i Et[j][i] * qsc[c][i]
    gemm_mma<false><<<dim3(2, 13, BATCH), 256, SMEM_B>>>(
        E, esc, attTq, N_PIX, N_PIX, CCH, CCH, NN, CN, CN);
    gemm_mma<false><<<dim3(2, 13, BATCH), 256, SMEM_B>>>(
        Et, qsc, attTe, N_PIX, N_PIX, CCH, CCH, NN, CN, CN);

    // 3x3 SAME convs into concatenated output
    conv_mma<<<dim3(7, 4, 2 * BATCH), 256, SMEM_B>>>(attTe, attTq, wT, out);
}

// round 7
// speedup vs baseline: 1.6080x; 1.0646x over previous
#include <cuda_runtime.h>
#include <cstdint>

#define N_PIX 1600
#define CCH   512
#define CORR  256
#define BATCH 16
#define NTILE 50    // N_PIX / 32

// ---------------- scratch (static __device__ arrays; allocation-free) -------
__device__ float g_inTe  [BATCH * N_PIX * CCH];            // exemplar^T [p][c] (tf32)
__device__ float g_inTq  [BATCH * N_PIX * CCH];            // query^T    [p][c] (tf32)
__device__ float g_qcorr [BATCH * N_PIX * CORR];           // (tf32)
__device__ float g_ecorr [BATCH * N_PIX * CORR];           // (tf32)
__device__ float g_E     [(long)BATCH * N_PIX * N_PIX];    // exp(A) (tf32)
__device__ float g_Et    [(long)BATCH * N_PIX * N_PIX];    // E^T    (tf32)
__device__ float g_prow  [BATCH * NTILE * N_PIX];          // partial row sums
__device__ float g_pcol  [BATCH * NTILE * N_PIX];          // partial col sums
__device__ float g_rsE   [BATCH * N_PIX];                  // 1/rowsum(E)
__device__ float g_rsEt  [BATCH * N_PIX];                  // 1/colsum(E)
__device__ float g_esc   [BATCH * CCH * N_PIX];            // exemplar*invColsum (tf32)
__device__ float g_qsc   [BATCH * CCH * N_PIX];            // query*invRowsum (tf32)
__device__ float g_attTe [BATCH * N_PIX * CCH];            // (tf32)
__device__ float g_attTq [BATCH * N_PIX * CCH];            // (tf32)
__device__ float g_wT    [2 * 9 * CCH * CCH];              // [which][kyx][o][c] (tf32)
__device__ float g_w1    [2 * CORR * CCH];                 // (tf32)

// ---------------- helpers -----------------------------------------------------
__device__ __forceinline__ void mma8(float4& d, const uint32_t a[4],
                                     const uint32_t b[2]) {
    asm volatile(
        "mma.sync.aligned.m16n8k8.row.col.f32.tf32.tf32.f32 "
        "{%0,%1,%2,%3}, {%4,%5,%6,%7}, {%8,%9}, {%0,%1,%2,%3};"
        : "+f"(d.x), "+f"(d.y), "+f"(d.z), "+f"(d.w)
        : "r"(a[0]), "r"(a[1]), "r"(a[2]), "r"(a[3]), "r"(b[0]), "r"(b[1]));
}
__device__ __forceinline__ float cvt1(float v) {
    asm("cvt.rna.tf32.f32 %0, %0;" : "+f"(v));
    return v;
}
__device__ __forceinline__ float4 cvt4(float4 v) {
    v.x = cvt1(v.x); v.y = cvt1(v.y); v.z = cvt1(v.z); v.w = cvt1(v.w);
    return v;
}
__device__ __forceinline__ uint32_t s2u(const void* p) {
    return (uint32_t)__cvta_generic_to_shared(p);
}
__device__ __forceinline__ void cpasync16(uint32_t dst, const void* src,
                                          uint32_t sz) {
    asm volatile("cp.async.cg.shared.global [%0], [%1], 16, %2;"
                 :: "r"(dst), "l"(src), "r"(sz));
}
#define CP_COMMIT() asm volatile("cp.async.commit_group;" ::: "memory")
#define CP_WAIT(n)  asm volatile("cp.async.wait_group %0;" :: "n"(n) : "memory")

// smem geometry (floats): CTA tile 128x128, k-chunk 32
#define PITCH    36
#define AT_FL    (128 * PITCH)           // 4608 floats per operand tile
#define STAGE_FL (2 * AT_FL)             // 9216
#define STAGE_B  (STAGE_FL * 4)          // 36864
#define SMEM_B   (2 * STAGE_B)           // 73728  (2 CTAs/SM fit: 147456 < 227KB)

// ---------------- tf32 GEMM: C[m][n] = sum_k A[m][k]*B[n][k] ------------------
// CTA tile 128x128xK32, 128 threads (4 warps, 2x2), warp tile 64x64,
// cp.async double buffer, 2 CTAs/SM for fence overlap.
template<bool DO_EXP>
__global__ void __launch_bounds__(128, 2)
gemm_mma(const float* __restrict__ A, const float* __restrict__ B,
         float* __restrict__ C, int K, int MA, int NB, int ldc,
         long bA, long bB, long bC)
{
    extern __shared__ float sm[];
    const uint32_t smb = s2u(sm);
    const int tid = threadIdx.x;
    const int lane = tid & 31, wid = tid >> 5;
    const int wm = wid >> 1, wn = wid & 1;
    const int lg = lane >> 2, lt = lane & 3;
    A += (long)blockIdx.z * bA;
    B += (long)blockIdx.z * bB;
    C += (long)blockIdx.z * bC;
    const int m0 = blockIdx.y * 128, n0 = blockIdx.x * 128;

    const int lrow = tid >> 3;          // 0..15
    const int lf4  = tid & 7;

    const float* Abase = A + (long)(m0 + lrow) * K + lf4 * 4;
    const float* Bbase = B + (long)(n0 + lrow) * K + lf4 * 4;
    const uint32_t dbase = lrow * (PITCH * 4) + lf4 * 16;

    float4 acc[4][8];
#pragma unroll
    for (int i = 0; i < 4; i++)
#pragma unroll
        for (int j = 0; j < 8; j++) acc[i][j] = make_float4(0.f, 0.f, 0.f, 0.f);

    const int nk = K >> 5;

    auto issue = [&](int koff, uint32_t sa) {
#pragma unroll
        for (int it = 0; it < 8; it++) {
            const int row = lrow + it * 16;
            cpasync16(sa + dbase + it * (16 * PITCH * 4),
                      Abase + (long)(it * 16) * K + koff,
                      (m0 + row) < MA ? 16u : 0u);
            cpasync16(sa + AT_FL * 4 + dbase + it * (16 * PITCH * 4),
                      Bbase + (long)(it * 16) * K + koff,
                      (n0 + row) < NB ? 16u : 0u);
        }
        CP_COMMIT();
    };

    issue(0, smb);
    for (int ck = 0; ck < nk; ck++) {
        if (ck + 1 < nk) {
            issue((ck + 1) * 32, smb + ((ck + 1) & 1) * STAGE_B);
            CP_WAIT(1);
        } else {
            CP_WAIT(0);
        }
        __syncthreads();

        const float* As = sm + (ck & 1) * STAGE_FL;
        const float* Bs = As + AT_FL;
#pragma unroll
        for (int ks = 0; ks < 4; ks++) {
            uint32_t af[4][4], bf[8][2];
#pragma unroll
            for (int mt = 0; mt < 4; mt++) {
                const float* p = As + (wm * 64 + mt * 16 + lg) * PITCH + ks * 8 + lt;
                af[mt][0] = __float_as_uint(p[0]);
                af[mt][1] = __float_as_uint(p[8 * PITCH]);
                af[mt][2] = __float_as_uint(p[4]);
                af[mt][3] = __float_as_uint(p[8 * PITCH + 4]);
            }
#pragma unroll
            for (int nt = 0; nt < 8; nt++) {
                const float* p = Bs + (wn * 64 + nt * 8 + lg) * PITCH + ks * 8 + lt;
                bf[nt][0] = __float_as_uint(p[0]);
                bf[nt][1] = __float_as_uint(p[4]);
            }
#pragma unroll
            for (int mt = 0; mt < 4; mt++)
#pragma unroll
                for (int nt = 0; nt < 8; nt++) mma8(acc[mt][nt], af[mt], bf[nt]);
        }
        __syncthreads();
    }

#pragma unroll
    for (int mt = 0; mt < 4; mt++) {
        const int r = m0 + wm * 64 + mt * 16 + lg;
#pragma unroll
        for (int nt = 0; nt < 8; nt++) {
            const int n = n0 + wn * 64 + nt * 8 + 2 * lt;
            float4 v = acc[mt][nt];
            if (DO_EXP) {
                v.x = __expf(v.x); v.y = __expf(v.y);
                v.z = __expf(v.z); v.w = __expf(v.w);
            }
            v = cvt4(v);
            if (n < NB) {
                if (r < MA)
                    *(float2*)(C + (long)r * ldc + n) = make_float2(v.x, v.y);
                if (r + 8 < MA)
                    *(float2*)(C + (long)(r + 8) * ldc + n) = make_float2(v.z, v.w);
            }
        }
    }
}

// ---------------- conv 3x3 SAME via implicit GEMM ----------------------------
// out[o][p] = sum_{kyx,c} wT[which][kyx][o][c] * inT[p+shift][c]
__global__ void __launch_bounds__(128, 2)
conv_mma(const float* __restrict__ attTe, const float* __restrict__ attTq,
         const float* __restrict__ wT, float* __restrict__ out)
{
    extern __shared__ float sm[];
    const uint32_t smb = s2u(sm);
    const int tid = threadIdx.x;
    const int lane = tid & 31, wid = tid >> 5;
    const int wm = wid >> 1, wn = wid & 1;
    const int lg = lane >> 2, lt = lane & 3;
    const int z = blockIdx.z;
    const int b = z & 15, which = z >> 4;
    const float* inT = (which ? attTq : attTe) + (long)b * N_PIX * CCH;
    const float* wbase = wT + (long)which * 9 * CCH * CCH;
    const int m0 = blockIdx.y * 128;    // out-channel block (512/128 = 4 exact)
    const int n0 = blockIdx.x * 128;    // pixel block (13 blocks cover 1600)

    const int lrow = tid >> 3;
    const int lf4  = tid & 7;
    const uint32_t dbase = lrow * (PITCH * 4) + lf4 * 16;

    int py_[8], px_[8];
    bool pv_[8];
#pragma unroll
    for (int it = 0; it < 8; it++) {
        int p = n0 + lrow + it * 16;
        py_[it] = p / 40; px_[it] = p % 40;
        pv_[it] = (p < N_PIX);
    }

    float4 acc[4][8];
#pragma unroll
    for (int i = 0; i < 4; i++)
#pragma unroll
        for (int j = 0; j < 8; j++) acc[i][j] = make_float4(0.f, 0.f, 0.f, 0.f);

    const int nk = 144;   // 9 kyx * 16 c-chunks

    auto issue = [&](int ck, uint32_t sa) {
        const int kyx = ck >> 4;
        const int cc = (ck & 15) * 32;
        const int dy = kyx / 3 - 1, dx = kyx % 3 - 1;
        const float* wk = wbase + (long)kyx * (CCH * CCH) + cc
                          + (m0 + lrow) * CCH + lf4 * 4;
#pragma unroll
        for (int it = 0; it < 8; it++) {
            cpasync16(sa + dbase + it * (16 * PITCH * 4),
                      wk + it * (16 * CCH), 16u);
            int ys = py_[it] + dy, xs = px_[it] + dx;
            bool ok = pv_[it] && (unsigned)ys < 40u && (unsigned)xs < 40u;
            const float* src = inT + (long)(ys * 40 + xs) * CCH + cc + lf4 * 4;
            cpasync16(sa + AT_FL * 4 + dbase + it * (16 * PITCH * 4),
                      src, ok ? 16u : 0u);
        }
        CP_COMMIT();
    };

    issue(0, smb);
    for (int ck = 0; ck < nk; ck++) {
        if (ck + 1 < nk) {
            issue(ck + 1, smb + ((ck + 1) & 1) * STAGE_B);
            CP_WAIT(1);
        } else {
            CP_WAIT(0);
        }
        __syncthreads();

        const float* As = sm + (ck & 1) * STAGE_FL;
        const float* Bs = As + AT_FL;
#pragma unroll
        for (int ks = 0; ks < 4; ks++) {
            uint32_t af[4][4], bf[8][2];
#pragma unroll
            for (int mt = 0; mt < 4; mt++) {
                const float* p = As + (wm * 64 + mt * 16 + lg) * PITCH + ks * 8 + lt;
                af[mt][0] = __float_as_uint(p[0]);
                af[mt][1] = __float_as_uint(p[8 * PITCH]);
                af[mt][2] = __float_as_uint(p[4]);
                af[mt][3] = __float_as_uint(p[8 * PITCH + 4]);
            }
#pragma unroll
            for (int nt = 0; nt < 8; nt++) {
                const float* p = Bs + (wn * 64 + nt * 8 + lg) * PITCH + ks * 8 + lt;
                bf[nt][0] = __float_as_uint(p[0]);
                bf[nt][1] = __float_as_uint(p[4]);
            }
#pragma unroll
            for (int mt = 0; mt < 4; mt++)
#pragma unroll
                for (int nt = 0; nt < 8; nt++) mma8(acc[mt][nt], af[mt], bf[nt]);
        }
        __syncthreads();
    }

    float* obase = out + ((long)b * 2 * CCH + (long)which * CCH) * N_PIX;
#pragma unroll
    for (int mt = 0; mt < 4; mt++) {
        const int r = m0 + wm * 64 + mt * 16 + lg;
#pragma unroll
        for (int nt = 0; nt < 8; nt++) {
            const int n = n0 + wn * 64 + nt * 8 + 2 * lt;
            if (n < N_PIX) {
                float4 v = acc[mt][nt];
                *(float2*)(obase + (long)r * N_PIX + n) = make_float2(v.x, v.y);
                *(float2*)(obase + (long)(r + 8) * N_PIX + n) = make_float2(v.z, v.w);
            }
        }
    }
}

// ------------- dual input transpose [c][p] -> [p][c] with tf32 cvt -----------
__global__ void transpose_in(const float* __restrict__ s0, float* __restrict__ d0,
                             const float* __restrict__ s1, float* __restrict__ d1)
{
    __shared__ float t[32][33];
    const int z = blockIdx.z;
    const int b = z & 15, which = z >> 4;
    const long CN = (long)CCH * N_PIX;
    const float* src = (which ? s1 : s0) + (long)b * CN;
    float* dst = (which ? d1 : d0) + (long)b * CN;
    const int x0 = blockIdx.x * 32, y0 = blockIdx.y * 32;
    const int tx = threadIdx.x, ty = threadIdx.y;
#pragma unroll
    for (int r = 0; r < 32; r += 8)
        t[ty + r][tx] = src[(long)(y0 + ty + r) * N_PIX + x0 + tx];
    __syncthreads();
#pragma unroll
    for (int r = 0; r < 32; r += 8)
        dst[(long)(x0 + ty + r) * CCH + y0 + tx] = cvt1(t[tx][ty + r]);
}

// ------- E transpose + per-tile row/col partial sums (deterministic) ---------
__global__ void transpose_es(const float* __restrict__ E, float* __restrict__ Et,
                             float* __restrict__ prow, float* __restrict__ pcol)
{
    __shared__ float t[32][33];
    const long NN = (long)N_PIX * N_PIX;
    const int bz = blockIdx.z;
    const float* src = E + bz * NN;
    float* dst = Et + bz * NN;
    const int x0 = blockIdx.x * 32, y0 = blockIdx.y * 32;
    const int tx = threadIdx.x, ty = threadIdx.y;   // (32, 8)
#pragma unroll
    for (int r = 0; r < 32; r += 8)
        t[ty + r][tx] = src[(long)(y0 + ty + r) * N_PIX + x0 + tx];
    __syncthreads();

    if (ty == 0) {          // row sums (global row y0+tx)
        float s = 0.f;
#pragma unroll 8
        for (int j = 0; j < 32; j++) s += t[tx][j];
        prow[((bz * NTILE) + blockIdx.x) * N_PIX + y0 + tx] = s;
    } else if (ty == 1) {   // col sums (global col x0+tx)
        float s = 0.f;
#pragma unroll 8
        for (int i = 0; i < 32; i++) s += t[i][tx];
        pcol[((bz * NTILE) + blockIdx.y) * N_PIX + x0 + tx] = s;
    }
#pragma unroll
    for (int r = 0; r < 32; r += 8)
        dst[(long)(x0 + ty + r) * N_PIX + y0 + tx] = t[tx][ty + r];
}

// ------------- reduce partials over 50 tiles and invert ----------------------
__global__ void reduce_inv(const float* __restrict__ prow,
                           const float* __restrict__ pcol,
                           float* __restrict__ rsE, float* __restrict__ rsEt)
{
    int idx = blockIdx.x * 256 + threadIdx.x;   // b*N_PIX + n
    if (idx >= BATCH * N_PIX) return;
    const int b = idx / N_PIX, n = idx % N_PIX;
    const float* src = (blockIdx.y ? pcol : prow) + (long)b * NTILE * N_PIX + n;
    float s = 0.f;
#pragma unroll 10
    for (int tgt = 0; tgt < NTILE; tgt++) s += src[(long)tgt * N_PIX];
    (blockIdx.y ? rsEt : rsE)[idx] = 1.f / s;
}

// esc = exemplar * invColsum(E)[i]; qsc = query * invRowsum(E)[i]  (tf32 out)
__global__ void scale_kernel(const float* __restrict__ ex,
                             const float* __restrict__ qu,
                             const float* __restrict__ invCs,
                             const float* __restrict__ invRs,
                             float* __restrict__ e2, float* __restrict__ q2)
{
    long idx = (long)blockIdx.x * 256 + threadIdx.x;
    if (idx >= (long)BATCH * CCH * N_PIX) return;
    int i = (int)(idx % N_PIX);
    int b = (int)(idx / ((long)CCH * N_PIX));
    e2[idx] = cvt1(ex[idx] * invCs[b * N_PIX + i]);
    q2[idx] = cvt1(qu[idx] * invRs[b * N_PIX + i]);
}

// ---------------- conv weights OIHW -> [which][kyx][o][c] (tf32) -------------
__global__ void wtrans_kernel(const float* __restrict__ w1,
                              const float* __restrict__ w2,
                              float* __restrict__ wT)
{
    long idx = (long)blockIdx.x * 256 + threadIdx.x;
    const long per = 9L * CCH * CCH;
    if (idx >= 2 * per) return;
    int c = (int)(idx & (CCH - 1));
    long t = idx >> 9;
    int o = (int)(t & (CCH - 1));
    long t2 = t >> 9;
    int kyx = (int)(t2 % 9);
    int which = (int)(t2 / 9);
    const float* w = which ? w2 : w1;
    wT[idx] = cvt1(w[((long)o * CCH + c) * 9 + kyx]);
}

// ---------------- 1x1 weights: copy w_q, w_e with tf32 rounding --------------
__global__ void w1cvt_kernel(const float* __restrict__ wq,
                             const float* __restrict__ we,
                             float* __restrict__ dst)
{
    int idx = blockIdx.x * 256 + threadIdx.x;
    if (idx >= 2 * CORR * CCH) return;
    const float* w = (idx < CORR * CCH) ? wq : we;
    dst[idx] = cvt1(w[idx < CORR * CCH ? idx : idx - CORR * CCH]);
}

// ---------------- launch ------------------------------------------------------
extern "C" void kernel_launch(void* const* d_in, const int* in_sizes, int n_in,
                              void* d_out, int out_size)
{
    const float* exemplar = (const float*)d_in[0];
    const float* query    = (const float*)d_in[1];
    const float* w_e      = (const float*)d_in[2];
    const float* w_q      = (const float*)d_in[3];
    const float* w_c1     = (const float*)d_in[4];
    const float* w_c2     = (const float*)d_in[5];
    float* out = (float*)d_out;

    float *inTe, *inTq, *qcorr, *ecorr, *E, *Et, *prow, *pcol, *rsE, *rsEt,
          *esc, *qsc, *attTe, *attTq, *wT, *w1;
    cudaGetSymbolAddress((void**)&inTe,  g_inTe);
    cudaGetSymbolAddress((void**)&inTq,  g_inTq);
    cudaGetSymbolAddress((void**)&qcorr, g_qcorr);
    cudaGetSymbolAddress((void**)&ecorr, g_ecorr);
    cudaGetSymbolAddress((void**)&E,     g_E);
    cudaGetSymbolAddress((void**)&Et,    g_Et);
    cudaGetSymbolAddress((void**)&prow,  g_prow);
    cudaGetSymbolAddress((void**)&pcol,  g_pcol);
    cudaGetSymbolAddress((void**)&rsE,   g_rsE);
    cudaGetSymbolAddress((void**)&rsEt,  g_rsEt);
    cudaGetSymbolAddress((void**)&esc,   g_esc);
    cudaGetSymbolAddress((void**)&qsc,   g_qsc);
    cudaGetSymbolAddress((void**)&attTe, g_attTe);
    cudaGetSymbolAddress((void**)&attTq, g_attTq);
    cudaGetSymbolAddress((void**)&wT,    g_wT);
    cudaGetSymbolAddress((void**)&w1,    g_w1);

    cudaFuncSetAttribute(gemm_mma<false>,
                         cudaFuncAttributeMaxDynamicSharedMemorySize, SMEM_B);
    cudaFuncSetAttribute(gemm_mma<true>,
                         cudaFuncAttributeMaxDynamicSharedMemorySize, SMEM_B);
    cudaFuncSetAttribute(conv_mma,
                         cudaFuncAttributeMaxDynamicSharedMemorySize, SMEM_B);

    const long NN = (long)N_PIX * N_PIX;
    const long CN = (long)CCH * N_PIX;
    const long NK = (long)N_PIX * CORR;

    // weight re-layouts (tf32)
    wtrans_kernel<<<(unsigned)((2L * 9 * CCH * CCH + 255) / 256), 256>>>(w_c1, w_c2, wT);
    w1cvt_kernel<<<(2 * CORR * CCH + 255) / 256, 256>>>(w_q, w_e, w1);

    // input transposes [c][p] -> [p][c] (tf32), both in one launch
    transpose_in<<<dim3(NTILE, 16, 32), dim3(32, 8)>>>(exemplar, inTe, query, inTq);

    // 1x1 projections: corr[p][o] = sum_c inT[p][c] * w[o][c]
    gemm_mma<false><<<dim3(2, 13, BATCH), 128, SMEM_B>>>(
        inTq, w1, qcorr, CCH, N_PIX, CORR, CORR, CN, 0L, NK);
    gemm_mma<false><<<dim3(2, 13, BATCH), 128, SMEM_B>>>(
        inTe, w1 + (long)CORR * CCH, ecorr, CCH, N_PIX, CORR, CORR, CN, 0L, NK);

    // E[n][m] = exp( sum_k ecorr[n][k] * qcorr[m][k] )
    gemm_mma<true><<<dim3(13, 13, BATCH), 128, SMEM_B>>>(
        ecorr, qcorr, E, CORR, N_PIX, N_PIX, N_PIX, NK, NK, NN);

    // Et = E^T, fused per-tile row/col partial sums
    transpose_es<<<dim3(NTILE, NTILE, BATCH), dim3(32, 8)>>>(E, Et, prow, pcol);
    reduce_inv<<<dim3((BATCH * N_PIX + 255) / 256, 2), 256>>>(prow, pcol, rsE, rsEt);

    // scaled inputs (softmax denominators folded into the small operand)
    scale_kernel<<<(unsigned)(((long)BATCH * CCH * N_PIX + 255) / 256), 256>>>(
        exemplar, query, rsEt, rsE, esc, qsc);

    // attention GEMMs, operand-swapped -> transposed outputs directly:
    //   attTq[j][c] = sum_i E[j][i]  * esc[c][i]
    //   attTe[j][c] = sum_i Et[j][i] * qsc[c][i]
    gemm_mma<false><<<dim3(4, 13, BATCH), 128, SMEM_B>>>(
        E, esc, attTq, N_PIX, N_PIX, CCH, CCH, NN, CN, CN);
    gemm_mma<false><<<dim3(4, 13, BATCH), 128, SMEM_B>>>(
        Et, qsc, attTe, N_PIX, N_PIX, CCH, CCH, NN, CN, CN);

    // 3x3 SAME convs into concatenated output
    conv_mma<<<dim3(13, 4, 2 * BATCH), 128, SMEM_B>>>(attTe, attTq, wT, out);
}